// round 4
// baseline (speedup 1.0000x reference)
#include <cuda_runtime.h>
#include <cstdint>

// ---------------------------------------------------------------------------
// Problem constants
// ---------------------------------------------------------------------------
#define HW_ (128 * 128)
static constexpr int IMG = 128;
static constexpr int NB  = 304;          // 16 * 19 effective batch
static constexpr size_t BUF_ELEMS = (size_t)NB * 32 * HW_;   // 637.5 MB

// scratch ping-pong buffers (device bss — no allocation APIs)
__device__ float g_bufA[BUF_ELEMS];
__device__ float g_bufB[BUF_ELEMS];

// CH_IDX baked in (EDGES + per-edge channel pairs), 19 x 4
__constant__ int c_chidx[19][4] = {
    {1, 8, 19, 20}, {8, 9, 21, 22}, {9, 10, 23, 24}, {1, 11, 25, 26},
    {11, 12, 27, 28}, {12, 13, 29, 30}, {1, 2, 31, 32}, {2, 3, 33, 34},
    {3, 4, 35, 36}, {2, 16, 37, 38}, {1, 5, 39, 40}, {5, 6, 41, 42},
    {6, 7, 43, 44}, {5, 17, 45, 46}, {0, 1, 47, 48}, {0, 14, 49, 50},
    {0, 15, 51, 52}, {14, 16, 53, 54}, {15, 17, 55, 56}
};

// ---------------------------------------------------------------------------
// packed f32x2 helpers (FFMA2 path — 2x fp32 FMA throughput on sm_103a)
// ---------------------------------------------------------------------------
typedef unsigned long long u64;

__device__ __forceinline__ u64 pack2(float lo, float hi) {
    u64 r;
    asm("mov.b64 %0, {%1, %2};" : "=l"(r) : "f"(lo), "f"(hi));
    return r;
}
__device__ __forceinline__ void unpack2(u64 v, float& lo, float& hi) {
    asm("mov.b64 {%0, %1}, %2;" : "=f"(lo), "=f"(hi) : "l"(v));
}
__device__ __forceinline__ void ffma2(u64& d, u64 a, u64 b) {
    asm("fma.rn.f32x2 %0, %1, %2, %0;" : "+l"(d) : "l"(a), "l"(b));
}

// ---------------------------------------------------------------------------
// 5x5 "same" conv, relu.  Block: 256 threads, computes a 32x32 output tile for
// 16 output channels of one batch image.  Each thread: 4 rows x 1 col x 16 co.
// Accumulators packed f32x2 over channel pairs; weights read as 64-bit smem
// broadcasts.  Dynamic smem: [ weights CIN*25*16 | input tile 36*36 | bias 16 ]
// ---------------------------------------------------------------------------
template <int CIN, int COUT, bool GATHER>
__global__ __launch_bounds__(256) void conv5(const float* __restrict__ in,
                                             const float* __restrict__ w,
                                             const float* __restrict__ bias,
                                             float* __restrict__ out) {
    constexpr int CO     = 16;              // out channels per block
    constexpr int SW_SZ  = CIN * 25 * CO;   // weight floats
    extern __shared__ __align__(16) float smem[];
    float* s_w  = smem;                      // [ (ci*25+tap)*16 + co ]
    float* s_in = smem + SW_SZ;              // [36][36]
    float* s_b  = s_in + 36 * 36;            // [16]

    const int tid    = threadIdx.x;
    const int tile   = blockIdx.x;           // 0..15  (4x4 tiles over 128x128)
    const int g      = blockIdx.y;           // co group
    const int b      = blockIdx.z;           // 0..303
    const int tile_x = (tile & 3) * 32;
    const int tile_y = (tile >> 2) * 32;

    // stage weights for this co-group
    for (int idx = tid; idx < SW_SZ; idx += 256) {
        int co  = idx & 15;
        int r   = idx >> 4;
        int ci  = r / 25;
        int tap = r % 25;
        s_w[idx] = w[((size_t)(g * CO + co) * CIN + ci) * 25 + tap];
    }
    if (tid < CO) s_b[tid] = bias[g * CO + tid];

    const float* src;
    int e = 0;
    if (GATHER) {
        int n = b / 19;
        e = b - n * 19;
        src = in + (size_t)n * 57 * HW_;
    } else {
        src = in + (size_t)b * CIN * HW_;
    }

    const int tx = tid & 31;
    const int ty = tid >> 5;

    u64 acc[4][8];   // [row p][co pair]  each holds (co=2c, co=2c+1)
#pragma unroll
    for (int p = 0; p < 4; ++p)
#pragma unroll
        for (int c = 0; c < 8; ++c) acc[p][c] = 0ull;

    for (int ci = 0; ci < CIN; ++ci) {
        __syncthreads();   // protect previous iteration's s_in reads (& s_w on iter 0)
        const float* sp =
            GATHER ? (src + (size_t)c_chidx[e][ci] * HW_) : (src + (size_t)ci * HW_);
        for (int idx = tid; idx < 36 * 36; idx += 256) {
            int r  = idx / 36;
            int c  = idx - r * 36;
            int ih = tile_y + r - 2;
            int iw = tile_x + c - 2;
            float v = 0.0f;
            if ((unsigned)ih < 128u && (unsigned)iw < 128u) v = sp[ih * IMG + iw];
            s_in[idx] = v;
        }
        __syncthreads();

#pragma unroll
        for (int dx = 0; dx < 5; ++dx) {
            float col[8];
#pragma unroll
            for (int j = 0; j < 8; ++j)
                col[j] = s_in[(ty * 4 + j) * 36 + tx + dx];
            u64 dup[8];
#pragma unroll
            for (int j = 0; j < 8; ++j) dup[j] = pack2(col[j], col[j]);

#pragma unroll
            for (int dy = 0; dy < 5; ++dy) {
                const u64* wr =
                    reinterpret_cast<const u64*>(s_w + ((ci * 5 + dy) * 5 + dx) * CO);
#pragma unroll
                for (int c = 0; c < 8; ++c) {
                    u64 wp = wr[c];                 // (w[2c], w[2c+1]) broadcast
                    ffma2(acc[0][c], dup[dy + 0], wp);
                    ffma2(acc[1][c], dup[dy + 1], wp);
                    ffma2(acc[2][c], dup[dy + 2], wp);
                    ffma2(acc[3][c], dup[dy + 3], wp);
                }
            }
        }
    }

    // epilogue: bias + relu + store
    const int y0 = tile_y + ty * 4;
    const int x  = tile_x + tx;
    float* ob = out + ((size_t)b * COUT + g * CO) * HW_ + x;
#pragma unroll
    for (int p = 0; p < 4; ++p) {
        float* op = ob + (size_t)(y0 + p) * IMG;
#pragma unroll
        for (int c = 0; c < 8; ++c) {
            float v0, v1;
            unpack2(acc[p][c], v0, v1);
            v0 += s_b[2 * c];
            v1 += s_b[2 * c + 1];
            v0 = fmaxf(v0, 0.0f);
            v1 = fmaxf(v1, 0.0f);
            op[(size_t)(2 * c) * HW_]     = v0;
            op[(size_t)(2 * c + 1) * HW_] = v1;
        }
    }
}

// ---------------------------------------------------------------------------
// fused 1x1 convs: 32 -> 128 (relu) -> 2.  Block: 256 threads, 512 pixels of
// one image (thread t handles pixels p and p+256, packed as f32x2).
// Weights pre-duplicated into smem as (w,w) u64 pairs so the hot loop is pure
// LDS.64 + FFMA2.
// ---------------------------------------------------------------------------
__global__ __launch_bounds__(256) void conv56(const float* __restrict__ in,
                                              const float* __restrict__ w5,
                                              const float* __restrict__ b5,
                                              const float* __restrict__ w6,
                                              const float* __restrict__ b6,
                                              float* __restrict__ out) {
    __shared__ __align__(16) u64 s_w5[128 * 32];   // dup pairs, 32 KB
    __shared__ u64   s_w6[2 * 128];                // dup pairs
    __shared__ float s_b5[128];

    const int tid = threadIdx.x;
    const int b   = blockIdx.y;
    const int px0 = blockIdx.x * 512 + tid;        // second pixel at +256

    for (int i = tid; i < 128 * 32; i += 256) {
        float v = w5[i];
        s_w5[i] = pack2(v, v);
    }
    if (tid < 128) {
        float v0 = w6[tid];          // w6[0][tid]
        float v1 = w6[128 + tid];    // w6[1][tid]
        s_w6[tid]       = pack2(v0, v0);
        s_w6[128 + tid] = pack2(v1, v1);
        s_b5[tid]       = b5[tid];
    }
    __syncthreads();

    const float* ip = in + (size_t)b * 32 * HW_;
    u64 x2[32];
#pragma unroll
    for (int ci = 0; ci < 32; ++ci) {
        const float* p = ip + (size_t)ci * HW_ + px0;
        x2[ci] = pack2(p[0], p[256]);
    }

    u64 acc0 = pack2(b6[0], b6[0]);
    u64 acc1 = pack2(b6[1], b6[1]);

    for (int j = 0; j < 128; ++j) {
        float bj = s_b5[j];
        u64 h = pack2(bj, bj);
        const u64* wr = s_w5 + j * 32;
#pragma unroll
        for (int ci = 0; ci < 32; ++ci) ffma2(h, x2[ci], wr[ci]);
        float h0, h1;
        unpack2(h, h0, h1);
        h0 = fmaxf(h0, 0.0f);
        h1 = fmaxf(h1, 0.0f);
        u64 hr = pack2(h0, h1);
        ffma2(acc0, hr, s_w6[j]);
        ffma2(acc1, hr, s_w6[128 + j]);
    }

    float o00, o01, o10, o11;
    unpack2(acc0, o00, o01);
    unpack2(acc1, o10, o11);
    // out channel index for (b = n*19+e, oc) is b*2 + oc in the (N,38,H,W) view
    float* op = out + (size_t)b * 2 * HW_;
    op[px0]             = o00;
    op[px0 + 256]       = o01;
    op[HW_ + px0]       = o10;
    op[HW_ + px0 + 256] = o11;
}

// ---------------------------------------------------------------------------
// launch
// ---------------------------------------------------------------------------
extern "C" void kernel_launch(void* const* d_in, const int* in_sizes, int n_in,
                              void* d_out, int out_size) {
    const float* x  = (const float*)d_in[0];
    // d_in[1] = gnn_interations (unused; reference runs exactly one pass)
    const float* w0 = (const float*)d_in[2];
    const float* b0 = (const float*)d_in[3];
    const float* w1 = (const float*)d_in[4];
    const float* b1 = (const float*)d_in[5];
    const float* w2 = (const float*)d_in[6];
    const float* b2 = (const float*)d_in[7];
    const float* w3 = (const float*)d_in[8];
    const float* b3 = (const float*)d_in[9];
    const float* w4 = (const float*)d_in[10];
    const float* b4 = (const float*)d_in[11];
    const float* w5 = (const float*)d_in[12];
    const float* b5 = (const float*)d_in[13];
    const float* w6 = (const float*)d_in[14];
    const float* b6 = (const float*)d_in[15];

    float *bufA = nullptr, *bufB = nullptr;
    cudaGetSymbolAddress((void**)&bufA, g_bufA);
    cudaGetSymbolAddress((void**)&bufB, g_bufB);

    auto smem_bytes = [](int cin) { return (size_t)(cin * 25 * 16 + 36 * 36 + 16) * 4; };

    cudaFuncSetAttribute(conv5<4, 16, true>,
                         cudaFuncAttributeMaxDynamicSharedMemorySize, (int)smem_bytes(4));
    cudaFuncSetAttribute(conv5<16, 16, false>,
                         cudaFuncAttributeMaxDynamicSharedMemorySize, (int)smem_bytes(16));
    cudaFuncSetAttribute(conv5<16, 32, false>,
                         cudaFuncAttributeMaxDynamicSharedMemorySize, (int)smem_bytes(16));
    cudaFuncSetAttribute(conv5<32, 32, false>,
                         cudaFuncAttributeMaxDynamicSharedMemorySize, (int)smem_bytes(32));

    dim3 blk(256);
    conv5<4, 16, true><<<dim3(16, 1, NB), blk, smem_bytes(4)>>>(x, w0, b0, bufA);
    conv5<16, 16, false><<<dim3(16, 1, NB), blk, smem_bytes(16)>>>(bufA, w1, b1, bufB);
    conv5<16, 32, false><<<dim3(16, 2, NB), blk, smem_bytes(16)>>>(bufB, w2, b2, bufA);
    conv5<32, 32, false><<<dim3(16, 2, NB), blk, smem_bytes(32)>>>(bufA, w3, b3, bufB);
    conv5<32, 32, false><<<dim3(16, 2, NB), blk, smem_bytes(32)>>>(bufB, w4, b4, bufA);
    conv56<<<dim3(HW_ / 512, NB), blk>>>(bufA, w5, b5, w6, b6, (float*)d_out);
}

// round 5
// speedup vs baseline: 1.8787x; 1.8787x over previous
#include <cuda_runtime.h>
#include <cstdint>

// ---------------------------------------------------------------------------
// Problem constants
// ---------------------------------------------------------------------------
#define HW_ (128 * 128)
static constexpr int IMG = 128;
static constexpr int NB  = 304;          // 16 * 19 effective batch
static constexpr size_t BUF_ELEMS = (size_t)NB * 32 * HW_;

// scratch ping-pong buffers (device bss — no allocation APIs)
__device__ float g_bufA[BUF_ELEMS];
__device__ float g_bufB[BUF_ELEMS];

// CH_IDX baked in (EDGES + per-edge channel pairs), 19 x 4
__constant__ int c_chidx[19][4] = {
    {1, 8, 19, 20}, {8, 9, 21, 22}, {9, 10, 23, 24}, {1, 11, 25, 26},
    {11, 12, 27, 28}, {12, 13, 29, 30}, {1, 2, 31, 32}, {2, 3, 33, 34},
    {3, 4, 35, 36}, {2, 16, 37, 38}, {1, 5, 39, 40}, {5, 6, 41, 42},
    {6, 7, 43, 44}, {5, 17, 45, 46}, {0, 1, 47, 48}, {0, 14, 49, 50},
    {0, 15, 51, 52}, {14, 16, 53, 54}, {15, 17, 55, 56}
};

// ---------------------------------------------------------------------------
// packed f32x2 helpers (FFMA2 path — 2x fp32 FMA throughput on sm_103a)
// ---------------------------------------------------------------------------
typedef unsigned long long u64;

__device__ __forceinline__ u64 pack2(float lo, float hi) {
    u64 r;
    asm("mov.b64 %0, {%1, %2};" : "=l"(r) : "f"(lo), "f"(hi));
    return r;
}
__device__ __forceinline__ void unpack2(u64 v, float& lo, float& hi) {
    asm("mov.b64 {%0, %1}, %2;" : "=f"(lo), "=f"(hi) : "l"(v));
}
__device__ __forceinline__ void ffma2(u64& d, u64 a, u64 b) {
    asm("fma.rn.f32x2 %0, %1, %2, %0;" : "+l"(d) : "l"(a), "l"(b));
}

// ---------------------------------------------------------------------------
// 5x5 "same" conv, relu.  Block: 256 threads, 32x32 output tile, 16 out
// channels.  Each thread: 4 rows x 1 col x 16 co, accumulators packed f32x2
// over channel pairs.  Input tile is DOUBLE-BUFFERED across ci: LDGs for ci+1
// are issued before the compute phase (latency hidden under ~1600 cyc of
// FFMA2), STS after, one barrier per ci.  Weights read as 128-bit LDS.
// smem: [ weights CIN*25*16 | input tile 2*36*36 | bias 16 ]
// ---------------------------------------------------------------------------
template <int CIN, int COUT, bool GATHER>
__global__ __launch_bounds__(256) void conv5(const float* __restrict__ in,
                                             const float* __restrict__ w,
                                             const float* __restrict__ bias,
                                             float* __restrict__ out) {
    constexpr int CO    = 16;
    constexpr int SW_SZ = CIN * 25 * CO;
    constexpr int TILE  = 36 * 36;           // 1296
    extern __shared__ __align__(16) float smem[];
    float* s_w  = smem;                      // [ (ci*25+tap)*16 + co ]
    float* s_in = smem + SW_SZ;              // 2 x [36][36]
    float* s_b  = s_in + 2 * TILE;           // [16]

    const int tid    = threadIdx.x;
    const int tile   = blockIdx.x;           // 0..15  (4x4 tiles over 128x128)
    const int g      = blockIdx.y;           // co group
    const int b      = blockIdx.z;           // 0..303
    const int tile_x = (tile & 3) * 32;
    const int tile_y = (tile >> 2) * 32;

    // stage weights for this co-group
    for (int idx = tid; idx < SW_SZ; idx += 256) {
        int co  = idx & 15;
        int r   = idx >> 4;
        int ci  = r / 25;
        int tap = r % 25;
        s_w[idx] = w[((size_t)(g * CO + co) * CIN + ci) * 25 + tap];
    }
    if (tid < CO) s_b[tid] = bias[g * CO + tid];

    const float* src;
    int e = 0;
    if (GATHER) {
        int n = b / 19;
        e = b - n * 19;
        src = in + (size_t)n * 57 * HW_;
    } else {
        src = in + (size_t)b * CIN * HW_;
    }

    // precompute halo-load offsets (ci-invariant): 6 elements per thread
    int  off[6];
    bool ok[6];
#pragma unroll
    for (int k = 0; k < 6; ++k) {
        int idx = tid + k * 256;
        int r   = idx / 36;
        int c   = idx - r * 36;
        int ih  = tile_y + r - 2;
        int iw  = tile_x + c - 2;
        ok[k]  = (idx < TILE) && ((unsigned)ih < 128u) && ((unsigned)iw < 128u);
        off[k] = ih * IMG + iw;
    }

    const int tx = tid & 31;
    const int ty = tid >> 5;

    u64 acc[4][8];   // [row p][co pair]
#pragma unroll
    for (int p = 0; p < 4; ++p)
#pragma unroll
        for (int c = 0; c < 8; ++c) acc[p][c] = 0ull;

    // prologue: load ci=0 tile
    float pre[6];
    {
        const float* sp =
            GATHER ? (src + (size_t)c_chidx[e][0] * HW_) : src;
#pragma unroll
        for (int k = 0; k < 6; ++k) pre[k] = ok[k] ? sp[off[k]] : 0.0f;
#pragma unroll
        for (int k = 0; k < 6; ++k)
            if (k < 5 || tid < (TILE - 5 * 256)) s_in[tid + k * 256] = pre[k];
    }
    __syncthreads();     // covers weights + first tile

    for (int ci = 0; ci < CIN; ++ci) {
        // issue prefetch LDGs for ci+1 (completion overlapped with compute)
        if (ci + 1 < CIN) {
            const float* sp = GATHER ? (src + (size_t)c_chidx[e][ci + 1] * HW_)
                                     : (src + (size_t)(ci + 1) * HW_);
#pragma unroll
            for (int k = 0; k < 6; ++k) pre[k] = ok[k] ? sp[off[k]] : 0.0f;
        }

        const float* cb    = s_in + (ci & 1) * TILE;
        const float* wbase = s_w + ci * 25 * CO;

#pragma unroll
        for (int dx = 0; dx < 5; ++dx) {
            u64 dup[8];
#pragma unroll
            for (int j = 0; j < 8; ++j) {
                float v = cb[(ty * 4 + j) * 36 + tx + dx];
                dup[j]  = pack2(v, v);
            }
#pragma unroll
            for (int dy = 0; dy < 5; ++dy) {
                const ulonglong2* wr =
                    reinterpret_cast<const ulonglong2*>(wbase + (dy * 5 + dx) * CO);
#pragma unroll
                for (int c2 = 0; c2 < 4; ++c2) {
                    ulonglong2 wp = wr[c2];   // 128-bit LDS, broadcast
                    ffma2(acc[0][2 * c2],     dup[dy + 0], wp.x);
                    ffma2(acc[0][2 * c2 + 1], dup[dy + 0], wp.y);
                    ffma2(acc[1][2 * c2],     dup[dy + 1], wp.x);
                    ffma2(acc[1][2 * c2 + 1], dup[dy + 1], wp.y);
                    ffma2(acc[2][2 * c2],     dup[dy + 2], wp.x);
                    ffma2(acc[2][2 * c2 + 1], dup[dy + 2], wp.y);
                    ffma2(acc[3][2 * c2],     dup[dy + 3], wp.x);
                    ffma2(acc[3][2 * c2 + 1], dup[dy + 3], wp.y);
                }
            }
        }

        // commit prefetched tile to the other buffer
        if (ci + 1 < CIN) {
            float* nb = s_in + ((ci + 1) & 1) * TILE;
#pragma unroll
            for (int k = 0; k < 6; ++k)
                if (k < 5 || tid < (TILE - 5 * 256)) nb[tid + k * 256] = pre[k];
        }
        __syncthreads();
    }

    // epilogue: bias + relu + store
    const int y0 = tile_y + ty * 4;
    const int x  = tile_x + tx;
    float* ob = out + ((size_t)b * COUT + g * CO) * HW_ + x;
#pragma unroll
    for (int p = 0; p < 4; ++p) {
        float* op = ob + (size_t)(y0 + p) * IMG;
#pragma unroll
        for (int c = 0; c < 8; ++c) {
            float v0, v1;
            unpack2(acc[p][c], v0, v1);
            v0 += s_b[2 * c];
            v1 += s_b[2 * c + 1];
            v0 = fmaxf(v0, 0.0f);
            v1 = fmaxf(v1, 0.0f);
            op[(size_t)(2 * c) * HW_]     = v0;
            op[(size_t)(2 * c + 1) * HW_] = v1;
        }
    }
}

// ---------------------------------------------------------------------------
// fused 1x1 convs: 32 -> 128 (relu) -> 2.  Block: 256 threads, 512 pixels of
// one image (thread t handles pixels p and p+256, packed as f32x2).
// Weights pre-duplicated into smem as (w,w) u64 pairs; hot loop reads them
// 128 bits at a time.
// ---------------------------------------------------------------------------
__global__ __launch_bounds__(256) void conv56(const float* __restrict__ in,
                                              const float* __restrict__ w5,
                                              const float* __restrict__ b5,
                                              const float* __restrict__ w6,
                                              const float* __restrict__ b6,
                                              float* __restrict__ out) {
    __shared__ __align__(16) u64 s_w5[128 * 32];   // dup pairs, 32 KB
    __shared__ __align__(16) u64 s_w6[2 * 128];    // dup pairs
    __shared__ float s_b5[128];

    const int tid = threadIdx.x;
    const int b   = blockIdx.y;
    const int px0 = blockIdx.x * 512 + tid;        // second pixel at +256

    for (int i = tid; i < 128 * 32; i += 256) {
        float v = w5[i];
        s_w5[i] = pack2(v, v);
    }
    if (tid < 128) {
        float v0 = w6[tid];          // w6[0][tid]
        float v1 = w6[128 + tid];    // w6[1][tid]
        s_w6[tid]       = pack2(v0, v0);
        s_w6[128 + tid] = pack2(v1, v1);
        s_b5[tid]       = b5[tid];
    }
    __syncthreads();

    const float* ip = in + (size_t)b * 32 * HW_;
    u64 x2[32];
#pragma unroll
    for (int ci = 0; ci < 32; ++ci) {
        const float* p = ip + (size_t)ci * HW_ + px0;
        x2[ci] = pack2(p[0], p[256]);
    }

    u64 acc0 = pack2(b6[0], b6[0]);
    u64 acc1 = pack2(b6[1], b6[1]);

    for (int j = 0; j < 128; ++j) {
        float bj = s_b5[j];
        u64 h = pack2(bj, bj);
        const ulonglong2* wr = reinterpret_cast<const ulonglong2*>(s_w5 + j * 32);
#pragma unroll
        for (int c2 = 0; c2 < 16; ++c2) {
            ulonglong2 wp = wr[c2];            // 128-bit LDS, broadcast
            ffma2(h, x2[2 * c2],     wp.x);
            ffma2(h, x2[2 * c2 + 1], wp.y);
        }
        float h0, h1;
        unpack2(h, h0, h1);
        h0 = fmaxf(h0, 0.0f);
        h1 = fmaxf(h1, 0.0f);
        u64 hr = pack2(h0, h1);
        ffma2(acc0, hr, s_w6[j]);
        ffma2(acc1, hr, s_w6[128 + j]);
    }

    float o00, o01, o10, o11;
    unpack2(acc0, o00, o01);
    unpack2(acc1, o10, o11);
    float* op = out + (size_t)b * 2 * HW_;
    op[px0]             = o00;
    op[px0 + 256]       = o01;
    op[HW_ + px0]       = o10;
    op[HW_ + px0 + 256] = o11;
}

// ---------------------------------------------------------------------------
// launch
// ---------------------------------------------------------------------------
extern "C" void kernel_launch(void* const* d_in, const int* in_sizes, int n_in,
                              void* d_out, int out_size) {
    const float* x  = (const float*)d_in[0];
    // d_in[1] = gnn_interations (unused; reference runs exactly one pass)
    const float* w0 = (const float*)d_in[2];
    const float* b0 = (const float*)d_in[3];
    const float* w1 = (const float*)d_in[4];
    const float* b1 = (const float*)d_in[5];
    const float* w2 = (const float*)d_in[6];
    const float* b2 = (const float*)d_in[7];
    const float* w3 = (const float*)d_in[8];
    const float* b3 = (const float*)d_in[9];
    const float* w4 = (const float*)d_in[10];
    const float* b4 = (const float*)d_in[11];
    const float* w5 = (const float*)d_in[12];
    const float* b5 = (const float*)d_in[13];
    const float* w6 = (const float*)d_in[14];
    const float* b6 = (const float*)d_in[15];

    float *bufA = nullptr, *bufB = nullptr;
    cudaGetSymbolAddress((void**)&bufA, g_bufA);
    cudaGetSymbolAddress((void**)&bufB, g_bufB);

    auto smem_bytes = [](int cin) {
        return (size_t)(cin * 25 * 16 + 2 * 36 * 36 + 16) * 4;
    };

    cudaFuncSetAttribute(conv5<4, 16, true>,
                         cudaFuncAttributeMaxDynamicSharedMemorySize, (int)smem_bytes(4));
    cudaFuncSetAttribute(conv5<16, 16, false>,
                         cudaFuncAttributeMaxDynamicSharedMemorySize, (int)smem_bytes(16));
    cudaFuncSetAttribute(conv5<16, 32, false>,
                         cudaFuncAttributeMaxDynamicSharedMemorySize, (int)smem_bytes(16));
    cudaFuncSetAttribute(conv5<32, 32, false>,
                         cudaFuncAttributeMaxDynamicSharedMemorySize, (int)smem_bytes(32));

    dim3 blk(256);
    conv5<4, 16, true><<<dim3(16, 1, NB), blk, smem_bytes(4)>>>(x, w0, b0, bufA);
    conv5<16, 16, false><<<dim3(16, 1, NB), blk, smem_bytes(16)>>>(bufA, w1, b1, bufB);
    conv5<16, 32, false><<<dim3(16, 2, NB), blk, smem_bytes(16)>>>(bufB, w2, b2, bufA);
    conv5<32, 32, false><<<dim3(16, 2, NB), blk, smem_bytes(32)>>>(bufA, w3, b3, bufB);
    conv5<32, 32, false><<<dim3(16, 2, NB), blk, smem_bytes(32)>>>(bufB, w4, b4, bufA);
    conv56<<<dim3(HW_ / 512, NB), blk>>>(bufA, w5, b5, w6, b6, (float*)d_out);
}

// round 6
// speedup vs baseline: 2.1057x; 1.1208x over previous
#include <cuda_runtime.h>
#include <cstdint>

// ---------------------------------------------------------------------------
// Problem constants
// ---------------------------------------------------------------------------
#define HW_ (128 * 128)
static constexpr int IMG = 128;
static constexpr int NB  = 304;          // 16 * 19 effective batch
static constexpr size_t BUF_ELEMS = (size_t)NB * 32 * HW_;

// scratch ping-pong buffers (device bss — no allocation APIs)
__device__ float g_bufA[BUF_ELEMS];
__device__ float g_bufB[BUF_ELEMS];

// CH_IDX baked in (EDGES + per-edge channel pairs), 19 x 4
__constant__ int c_chidx[19][4] = {
    {1, 8, 19, 20}, {8, 9, 21, 22}, {9, 10, 23, 24}, {1, 11, 25, 26},
    {11, 12, 27, 28}, {12, 13, 29, 30}, {1, 2, 31, 32}, {2, 3, 33, 34},
    {3, 4, 35, 36}, {2, 16, 37, 38}, {1, 5, 39, 40}, {5, 6, 41, 42},
    {6, 7, 43, 44}, {5, 17, 45, 46}, {0, 1, 47, 48}, {0, 14, 49, 50},
    {0, 15, 51, 52}, {14, 16, 53, 54}, {15, 17, 55, 56}
};

// ---------------------------------------------------------------------------
// packed f32x2 helpers (FFMA2 path — 2x fp32 FMA throughput on sm_103a)
// ---------------------------------------------------------------------------
typedef unsigned long long u64;

__device__ __forceinline__ u64 pack2(float lo, float hi) {
    u64 r;
    asm("mov.b64 %0, {%1, %2};" : "=l"(r) : "f"(lo), "f"(hi));
    return r;
}
__device__ __forceinline__ void unpack2(u64 v, float& lo, float& hi) {
    asm("mov.b64 {%0, %1}, %2;" : "=f"(lo), "=f"(hi) : "l"(v));
}
__device__ __forceinline__ void ffma2(u64& d, u64 a, u64 b) {
    asm("fma.rn.f32x2 %0, %1, %2, %0;" : "+l"(d) : "l"(a), "l"(b));
}

// cp.async helpers (LDGSTS with zero-fill for halo)
__device__ __forceinline__ void cpasync4(unsigned dst, const float* src, int sz) {
    asm volatile("cp.async.ca.shared.global [%0], [%1], 4, %2;"
                 :: "r"(dst), "l"(src), "r"(sz));
}
__device__ __forceinline__ void cpasync_commit() {
    asm volatile("cp.async.commit_group;");
}
__device__ __forceinline__ void cpasync_wait_all() {
    asm volatile("cp.async.wait_group 0;" ::: "memory");
}

// ---------------------------------------------------------------------------
// 5x5 "same" conv, relu.  Block: 256 threads, 32x32 output tile, 8 out
// channels (CO=8) so accumulators fit in 32 regs -> 3 blocks/SM (24 warps).
// Each thread: 4 rows x 1 col x 8 co, accumulators packed f32x2 over channel
// pairs.  Input tile double-buffered across ci via cp.async (zfill halo);
// one barrier per ci.  Weights read as 128-bit LDS broadcasts.
// smem: [ weights CIN*25*8 | input tile 2*36*36 | bias 8 ]
// ---------------------------------------------------------------------------
template <int CIN, int COUT, bool GATHER>
__global__ __launch_bounds__(256, 3) void conv5(const float* __restrict__ in,
                                                const float* __restrict__ w,
                                                const float* __restrict__ bias,
                                                float* __restrict__ out) {
    constexpr int CO    = 8;
    constexpr int SW_SZ = CIN * 25 * CO;
    constexpr int TILE  = 36 * 36;           // 1296
    extern __shared__ __align__(16) float smem[];
    float* s_w  = smem;                      // [ (ci*25+tap)*8 + co ]
    float* s_in = smem + SW_SZ;              // 2 x [36][36]
    float* s_b  = s_in + 2 * TILE;           // [8]

    const int tid    = threadIdx.x;
    const int tile   = blockIdx.x;           // 0..15  (4x4 tiles over 128x128)
    const int g      = blockIdx.y;           // co group (8 channels each)
    const int b      = blockIdx.z;           // 0..303
    const int tile_x = (tile & 3) * 32;
    const int tile_y = (tile >> 2) * 32;

    // stage weights for this co-group
    for (int idx = tid; idx < SW_SZ; idx += 256) {
        int co  = idx & 7;
        int r   = idx >> 3;
        int ci  = r / 25;
        int tap = r % 25;
        s_w[idx] = w[((size_t)(g * CO + co) * CIN + ci) * 25 + tap];
    }
    if (tid < CO) s_b[tid] = bias[g * CO + tid];

    const float* src;
    int e = 0;
    if (GATHER) {
        int n = b / 19;
        e = b - n * 19;
        src = in + (size_t)n * 57 * HW_;
    } else {
        src = in + (size_t)b * CIN * HW_;
    }

    // precompute halo-load offsets (ci-invariant): up to 6 elements per thread
    int off[6];
    int szb[6];
#pragma unroll
    for (int k = 0; k < 6; ++k) {
        int idx  = tid + k * 256;
        int r    = idx / 36;
        int c    = idx - r * 36;
        int ih   = tile_y + r - 2;
        int iw   = tile_x + c - 2;
        bool v   = ((unsigned)ih < 128u) && ((unsigned)iw < 128u);
        szb[k]   = v ? 4 : 0;
        off[k]   = v ? (ih * IMG + iw) : 0;
    }

    const unsigned s_in_b = (unsigned)__cvta_generic_to_shared(s_in);
    const int tx = tid & 31;
    const int ty = tid >> 5;

    u64 acc[4][4];   // [row p][co pair]
#pragma unroll
    for (int p = 0; p < 4; ++p)
#pragma unroll
        for (int c = 0; c < 4; ++c) acc[p][c] = 0ull;

    // async stage of one channel tile into buffer bi
    auto stage = [&](int ci_n, int bi) {
        const float* sp = GATHER ? (src + (size_t)c_chidx[e][ci_n] * HW_)
                                 : (src + (size_t)ci_n * HW_);
        unsigned base = s_in_b + (unsigned)(bi * TILE * 4);
#pragma unroll
        for (int k = 0; k < 6; ++k) {
            int idx = tid + k * 256;
            if (k < 5 || tid < (TILE - 5 * 256))
                cpasync4(base + (unsigned)idx * 4u, sp + off[k], szb[k]);
        }
        cpasync_commit();
    };

    stage(0, 0);
    cpasync_wait_all();
    __syncthreads();     // covers weights + first tile

    for (int ci = 0; ci < CIN; ++ci) {
        if (ci + 1 < CIN) stage(ci + 1, (ci + 1) & 1);

        const float* cb    = s_in + (ci & 1) * TILE;
        const float* wbase = s_w + ci * 25 * CO;

#pragma unroll
        for (int dx = 0; dx < 5; ++dx) {
            u64 dup[8];
#pragma unroll
            for (int j = 0; j < 8; ++j) {
                float v = cb[(ty * 4 + j) * 36 + tx + dx];
                dup[j]  = pack2(v, v);
            }
#pragma unroll
            for (int dy = 0; dy < 5; ++dy) {
                const ulonglong2* wr =
                    reinterpret_cast<const ulonglong2*>(wbase + (dy * 5 + dx) * CO);
                ulonglong2 wp0 = wr[0];
                ulonglong2 wp1 = wr[1];
#pragma unroll
                for (int p = 0; p < 4; ++p) {
                    ffma2(acc[p][0], dup[dy + p], wp0.x);
                    ffma2(acc[p][1], dup[dy + p], wp0.y);
                    ffma2(acc[p][2], dup[dy + p], wp1.x);
                    ffma2(acc[p][3], dup[dy + p], wp1.y);
                }
            }
        }

        if (ci + 1 < CIN) {
            cpasync_wait_all();
            __syncthreads();
        }
    }

    // epilogue: bias + relu + store
    const int y0 = tile_y + ty * 4;
    const int x  = tile_x + tx;
    float* ob = out + ((size_t)b * COUT + g * CO) * HW_ + x;
#pragma unroll
    for (int p = 0; p < 4; ++p) {
        float* op = ob + (size_t)(y0 + p) * IMG;
#pragma unroll
        for (int c = 0; c < 4; ++c) {
            float v0, v1;
            unpack2(acc[p][c], v0, v1);
            v0 += s_b[2 * c];
            v1 += s_b[2 * c + 1];
            v0 = fmaxf(v0, 0.0f);
            v1 = fmaxf(v1, 0.0f);
            op[(size_t)(2 * c) * HW_]     = v0;
            op[(size_t)(2 * c + 1) * HW_] = v1;
        }
    }
}

// ---------------------------------------------------------------------------
// fused 1x1 convs: 32 -> 128 (relu) -> 2.  Block: 256 threads, 512 pixels of
// one image (thread t handles pixels p and p+256, packed as f32x2).
// Weights pre-duplicated into smem as (w,w) u64 pairs; hot loop reads them
// 128 bits at a time.
// ---------------------------------------------------------------------------
__global__ __launch_bounds__(256) void conv56(const float* __restrict__ in,
                                              const float* __restrict__ w5,
                                              const float* __restrict__ b5,
                                              const float* __restrict__ w6,
                                              const float* __restrict__ b6,
                                              float* __restrict__ out) {
    __shared__ __align__(16) u64 s_w5[128 * 32];   // dup pairs, 32 KB
    __shared__ __align__(16) u64 s_w6[2 * 128];    // dup pairs
    __shared__ float s_b5[128];

    const int tid = threadIdx.x;
    const int b   = blockIdx.y;
    const int px0 = blockIdx.x * 512 + tid;        // second pixel at +256

    for (int i = tid; i < 128 * 32; i += 256) {
        float v = w5[i];
        s_w5[i] = pack2(v, v);
    }
    if (tid < 128) {
        float v0 = w6[tid];          // w6[0][tid]
        float v1 = w6[128 + tid];    // w6[1][tid]
        s_w6[tid]       = pack2(v0, v0);
        s_w6[128 + tid] = pack2(v1, v1);
        s_b5[tid]       = b5[tid];
    }
    __syncthreads();

    const float* ip = in + (size_t)b * 32 * HW_;
    u64 x2[32];
#pragma unroll
    for (int ci = 0; ci < 32; ++ci) {
        const float* p = ip + (size_t)ci * HW_ + px0;
        x2[ci] = pack2(p[0], p[256]);
    }

    u64 acc0 = pack2(b6[0], b6[0]);
    u64 acc1 = pack2(b6[1], b6[1]);

    for (int j = 0; j < 128; ++j) {
        float bj = s_b5[j];
        u64 h = pack2(bj, bj);
        const ulonglong2* wr = reinterpret_cast<const ulonglong2*>(s_w5 + j * 32);
#pragma unroll
        for (int c2 = 0; c2 < 16; ++c2) {
            ulonglong2 wp = wr[c2];            // 128-bit LDS, broadcast
            ffma2(h, x2[2 * c2],     wp.x);
            ffma2(h, x2[2 * c2 + 1], wp.y);
        }
        float h0, h1;
        unpack2(h, h0, h1);
        h0 = fmaxf(h0, 0.0f);
        h1 = fmaxf(h1, 0.0f);
        u64 hr = pack2(h0, h1);
        ffma2(acc0, hr, s_w6[j]);
        ffma2(acc1, hr, s_w6[128 + j]);
    }

    float o00, o01, o10, o11;
    unpack2(acc0, o00, o01);
    unpack2(acc1, o10, o11);
    float* op = out + (size_t)b * 2 * HW_;
    op[px0]             = o00;
    op[px0 + 256]       = o01;
    op[HW_ + px0]       = o10;
    op[HW_ + px0 + 256] = o11;
}

// ---------------------------------------------------------------------------
// launch
// ---------------------------------------------------------------------------
extern "C" void kernel_launch(void* const* d_in, const int* in_sizes, int n_in,
                              void* d_out, int out_size) {
    const float* x  = (const float*)d_in[0];
    // d_in[1] = gnn_interations (unused; reference runs exactly one pass)
    const float* w0 = (const float*)d_in[2];
    const float* b0 = (const float*)d_in[3];
    const float* w1 = (const float*)d_in[4];
    const float* b1 = (const float*)d_in[5];
    const float* w2 = (const float*)d_in[6];
    const float* b2 = (const float*)d_in[7];
    const float* w3 = (const float*)d_in[8];
    const float* b3 = (const float*)d_in[9];
    const float* w4 = (const float*)d_in[10];
    const float* b4 = (const float*)d_in[11];
    const float* w5 = (const float*)d_in[12];
    const float* b5 = (const float*)d_in[13];
    const float* w6 = (const float*)d_in[14];
    const float* b6 = (const float*)d_in[15];

    float *bufA = nullptr, *bufB = nullptr;
    cudaGetSymbolAddress((void**)&bufA, g_bufA);
    cudaGetSymbolAddress((void**)&bufB, g_bufB);

    auto smem_bytes = [](int cin) {
        return (size_t)(cin * 25 * 8 + 2 * 36 * 36 + 8) * 4;
    };

    cudaFuncSetAttribute(conv5<4, 16, true>,
                         cudaFuncAttributeMaxDynamicSharedMemorySize, (int)smem_bytes(4));
    cudaFuncSetAttribute(conv5<16, 16, false>,
                         cudaFuncAttributeMaxDynamicSharedMemorySize, (int)smem_bytes(16));
    cudaFuncSetAttribute(conv5<16, 32, false>,
                         cudaFuncAttributeMaxDynamicSharedMemorySize, (int)smem_bytes(16));
    cudaFuncSetAttribute(conv5<32, 32, false>,
                         cudaFuncAttributeMaxDynamicSharedMemorySize, (int)smem_bytes(32));

    dim3 blk(256);
    conv5<4, 16, true><<<dim3(16, 2, NB), blk, smem_bytes(4)>>>(x, w0, b0, bufA);
    conv5<16, 16, false><<<dim3(16, 2, NB), blk, smem_bytes(16)>>>(bufA, w1, b1, bufB);
    conv5<16, 32, false><<<dim3(16, 4, NB), blk, smem_bytes(16)>>>(bufB, w2, b2, bufA);
    conv5<32, 32, false><<<dim3(16, 4, NB), blk, smem_bytes(32)>>>(bufA, w3, b3, bufB);
    conv5<32, 32, false><<<dim3(16, 4, NB), blk, smem_bytes(32)>>>(bufB, w4, b4, bufA);
    conv56<<<dim3(HW_ / 512, NB), blk>>>(bufA, w5, b5, w6, b6, (float*)d_out);
}